// round 12
// baseline (speedup 1.0000x reference)
#include <cuda_runtime.h>
#include <math.h>
#include <stdint.h>

#define BATCH 4
#define SEQ   2048
#define EMD   768
#define HEADS 8
#define HDIM  96
#define MROWS (BATCH*SEQ)

#define TQ 16
#define TK 16
#define KSPLIT 4
#define KCHUNK (SEQ/KSPLIT)
#define QSTR 776           // bf16 elements per row (1552 B) -> conflict-free frags
#define VSTR 772           // fp32 elements per row
#define ESTR 17
#define SQRT_EMD 27.712812921102035f

typedef unsigned long long ull;

__device__ __forceinline__ ull pk2(float lo, float hi) {
    ull r; asm("mov.b64 %0,{%1,%2};" : "=l"(r) : "f"(lo), "f"(hi)); return r;
}
__device__ __forceinline__ void upk2(ull v, float& lo, float& hi) {
    asm("mov.b64 {%0,%1},%2;" : "=f"(lo), "=f"(hi) : "l"(v));
}
#define FFMA2(d,a,b,c) asm("fma.rn.f32x2 %0,%1,%2,%3;" : "=l"(d) : "l"(a), "l"(b), "l"(c))

__device__ __forceinline__ uint32_t f2tf32(float x) {
    uint32_t r; asm("cvt.rna.tf32.f32 %0, %1;" : "=r"(r) : "f"(x)); return r;
}
// C(16x8,f32) += A(16x8,tf32,row) * B(8x8,tf32,col)
__device__ __forceinline__ void mma_tf32(float* d, const uint32_t* a, const uint32_t* b) {
    asm volatile(
        "mma.sync.aligned.m16n8k8.row.col.f32.tf32.tf32.f32 "
        "{%0,%1,%2,%3}, {%4,%5,%6,%7}, {%8,%9}, {%0,%1,%2,%3};"
        : "+f"(d[0]), "+f"(d[1]), "+f"(d[2]), "+f"(d[3])
        : "r"(a[0]), "r"(a[1]), "r"(a[2]), "r"(a[3]), "r"(b[0]), "r"(b[1]));
}
// C(16x8,f32) += A(16x16,bf16,row) * B(16x8,bf16,col)
__device__ __forceinline__ void mma_bf16(float* d, const uint32_t* a, const uint32_t* b) {
    asm volatile(
        "mma.sync.aligned.m16n8k16.row.col.f32.bf16.bf16.f32 "
        "{%0,%1,%2,%3}, {%4,%5,%6,%7}, {%8,%9}, {%0,%1,%2,%3};"
        : "+f"(d[0]), "+f"(d[1]), "+f"(d[2]), "+f"(d[3])
        : "r"(a[0]), "r"(a[1]), "r"(a[2]), "r"(a[3]), "r"(b[0]), "r"(b[1]));
}
__device__ __forceinline__ uint32_t bfx2(float lo, float hi) {
    uint32_t r; asm("cvt.rn.bf16x2.f32 %0, %1, %2;" : "=r"(r) : "f"(hi), "f"(lo)); return r;
}
// split (x,y) into hi-pair (bf16 rn) and lo-pair (residual as bf16)
__device__ __forceinline__ void split2(float x, float y, uint32_t& hp, uint32_t& lp) {
    const uint32_t bx = __float_as_uint(x), by = __float_as_uint(y);
    const uint32_t rx = (bx + 0x7FFFu + ((bx >> 16) & 1u)) & 0xFFFF0000u;
    const uint32_t ry = (by + 0x7FFFu + ((by >> 16) & 1u)) & 0xFFFF0000u;
    hp = ry | (rx >> 16);
    lp = bfx2(x - __uint_as_float(rx), y - __uint_as_float(ry));
}

// Scratch (allocation-free rule: __device__ globals)
__device__ float g_Q [MROWS*EMD];
__device__ float g_K [MROWS*EMD];
__device__ float g_V [MROWS*EMD];
__device__ float g_O0[MROWS*EMD];
__device__ float g_O1[MROWS*EMD];
__device__ float g_O2[MROWS*EMD];
__device__ float g_O3[MROWS*EMD];

// ---------------------------------------------------------------------------
// mma.sync tf32 NT GEMM (single A): C[m,n] = sum_k A[m,k]*W[n,k] + bias[n]
// 128x128 tile, BK=32, 8 warps (2M x 4N), warp tile 64x32, fp32 accumulate.
// 2 CTAs/SM. blockIdx.z selects (W,bias,C).   (unchanged from R11)
// ---------------------------------------------------------------------------
__global__ __launch_bounds__(256, 2)
void gemm_mma(const float* __restrict__ A,
              const float* __restrict__ W0, const float* __restrict__ bv0, float* __restrict__ C0,
              const float* __restrict__ W1, const float* __restrict__ bv1, float* __restrict__ C1,
              const float* __restrict__ W2, const float* __restrict__ bv2, float* __restrict__ C2)
{
    const float* W    = W0;
    const float* bias = bv0;
    float*       C    = C0;
    if (blockIdx.z == 1) { W = W1; bias = bv1; C = C1; }
    if (blockIdx.z == 2) { W = W2; bias = bv2; C = C2; }

    __shared__ __align__(16) uint32_t As[128][36];
    __shared__ __align__(16) uint32_t Bs[128][36];

    const int tid  = threadIdx.x;
    const int w    = tid >> 5;
    const int lane = tid & 31;
    const int wm   = w & 1;
    const int wn   = w >> 1;
    const int gid  = lane >> 2;
    const int tig  = lane & 3;
    const int m0   = blockIdx.x * 128;
    const int n0   = blockIdx.y * 128;

    const int lr = tid >> 1;
    const int lc = (tid & 1) * 16;

    const float* Ap = A + (size_t)(m0 + lr) * EMD + lc;
    const float* Wp = W + (size_t)(n0 + lr) * EMD + lc;

    float acc[4][4][4];
    #pragma unroll
    for (int i = 0; i < 4; i++)
        #pragma unroll
        for (int j = 0; j < 4; j++)
            #pragma unroll
            for (int r = 0; r < 4; r++) acc[i][j][r] = 0.f;

    for (int k0 = 0; k0 < EMD; k0 += 32) {
        #pragma unroll
        for (int ci = 0; ci < 4; ci++) {
            const float4 v  = *(const float4*)(Ap + k0 + ci*4);
            uint4 t;
            t.x = f2tf32(v.x); t.y = f2tf32(v.y); t.z = f2tf32(v.z); t.w = f2tf32(v.w);
            *(uint4*)&As[lr][lc + ci*4] = t;
            const float4 wv = *(const float4*)(Wp + k0 + ci*4);
            uint4 u;
            u.x = f2tf32(wv.x); u.y = f2tf32(wv.y); u.z = f2tf32(wv.z); u.w = f2tf32(wv.w);
            *(uint4*)&Bs[lr][lc + ci*4] = u;
        }
        __syncthreads();

        #pragma unroll
        for (int ks = 0; ks < 4; ks++) {
            uint32_t a[4][4], b[4][2];
            #pragma unroll
            for (int i = 0; i < 4; i++) {
                const uint32_t* ap = &As[wm*64 + i*16 + gid][ks*8 + tig];
                a[i][0] = ap[0];
                a[i][1] = ap[8*36];
                a[i][2] = ap[4];
                a[i][3] = ap[8*36 + 4];
            }
            #pragma unroll
            for (int j = 0; j < 4; j++) {
                const uint32_t* bp = &Bs[wn*32 + j*8 + gid][ks*8 + tig];
                b[j][0] = bp[0];
                b[j][1] = bp[4];
            }
            #pragma unroll
            for (int i = 0; i < 4; i++)
                #pragma unroll
                for (int j = 0; j < 4; j++)
                    mma_tf32(acc[i][j], a[i], b[j]);
        }
        __syncthreads();
    }

    #pragma unroll
    for (int i = 0; i < 4; i++) {
        const int m = m0 + wm*64 + i*16 + gid;
        #pragma unroll
        for (int j = 0; j < 4; j++) {
            const int n = n0 + wn*32 + j*8 + tig*2;
            const float2 bv = *(const float2*)&bias[n];
            float2 o0, o1;
            o0.x = acc[i][j][0] + bv.x; o0.y = acc[i][j][1] + bv.y;
            o1.x = acc[i][j][2] + bv.x; o1.y = acc[i][j][3] + bv.y;
            *(float2*)(C + (size_t)m*EMD + n)     = o0;
            *(float2*)(C + (size_t)(m+8)*EMD + n) = o1;
        }
    }
}

// ---------------------------------------------------------------------------
// Sum the 4 split-K partial O buffers into g_O0 (float4 grid-stride).
// ---------------------------------------------------------------------------
__global__ __launch_bounds__(256)
void presum_o()
{
    const size_t N = (size_t)MROWS * EMD / 4;
    float4*       o0 = (float4*)g_O0;
    const float4* o1 = (const float4*)g_O1;
    const float4* o2 = (const float4*)g_O2;
    const float4* o3 = (const float4*)g_O3;
    for (size_t i = (size_t)blockIdx.x * blockDim.x + threadIdx.x; i < N;
         i += (size_t)gridDim.x * blockDim.x) {
        float4 a = o0[i];
        const float4 b = o1[i], c = o2[i], d = o3[i];
        a.x = (a.x + b.x) + (c.x + d.x);
        a.y = (a.y + b.y) + (c.y + d.y);
        a.z = (a.z + b.z) + (c.z + d.z);
        a.w = (a.w + b.w) + (c.w + d.w);
        o0[i] = a;
    }
}

// ---------------------------------------------------------------------------
// Fused attention, softmax over HEADS axis. Split-K4, TQ=16, 2 CTAs/SM.
// E = Q K^T via split-bf16 m16n8k16 MMA.  V shares the K-plane buffer:
// K loaded for E, V loaded into the same region after the post-E barrier
// (exact: head-softmax has no k-coupling). AV via FFMA2.
// Smem: Qhi/Qlo bf16[16][776] (24832 each), K/V buf 49664, Es 8704 = 108032 B.
// CTA: (b, 16-row q-tile, k-quarter). 8 warps = 1 per head.
// ---------------------------------------------------------------------------
__global__ __launch_bounds__(256, 2)
void attn_kernel()
{
    extern __shared__ char smx[];
    char*  Qhi = smx;                       // 24832
    char*  Qlo = smx + 24832;               // 24832
    char*  KV  = smx + 49664;               // 49664: Khi(24832)+Klo(24832) OR V fp32
    char*  Khi = KV;
    char*  Klo = KV + 24832;
    float* Vs  = (float*)KV;                // 16*772*4 = 49408 <= 49664
    float* Es  = (float*)(smx + 99328);     // 8704

    const int b    = blockIdx.y;
    const int q0   = blockIdx.x * TQ;
    const int kh   = blockIdx.z;
    const int tid  = threadIdx.x;
    const int warp = tid >> 5;              // head
    const int lane = tid & 31;
    const int gid  = lane >> 2;             // 0..7 (mma group)
    const int tig  = lane & 3;              // 0..3
    const int qg   = lane >> 3;             // 0..3 (AV mapping)
    const int kg   = lane & 7;              // 0..7
    const int hb   = warp * HDIM;           // col base (elements)

    // ---- Q tile -> bf16 hi/lo planes (once per CTA) ----
    for (int j = tid; j < TQ*(EMD/4); j += 256) {
        const int r  = j / (EMD/4);
        const int c4 = j % (EMD/4);
        const float4 v = *(const float4*)(g_Q + (size_t)(b*SEQ + q0 + r)*EMD + c4*4);
        uint32_t h0, l0, h1, l1;
        split2(v.x, v.y, h0, l0);
        split2(v.z, v.w, h1, l1);
        uint2 hh; hh.x = h0; hh.y = h1;
        uint2 ll; ll.x = l0; ll.y = l1;
        *(uint2*)(Qhi + ((size_t)r*QSTR + c4*4)*2) = hh;
        *(uint2*)(Qlo + ((size_t)r*QSTR + c4*4)*2) = ll;
    }

    ull Oacc[4][6];
    #pragma unroll
    for (int i = 0; i < 4; i++)
        #pragma unroll
        for (int j = 0; j < 6; j++) Oacc[i][j] = 0ull;

    const int kbeg = kh * KCHUNK;
    for (int k0 = kbeg; k0 < kbeg + KCHUNK; k0 += TK) {
        __syncthreads();   // (a) prev AV reads of V/Es done; Q planes visible (iter 0)

        // ---- K tile -> bf16 hi/lo planes ----
        for (int j = tid; j < TK*(EMD/4); j += 256) {
            const int r  = j / (EMD/4);
            const int c4 = j % (EMD/4);
            const float4 kv = *(const float4*)(g_K + (size_t)(b*SEQ + k0 + r)*EMD + c4*4);
            uint32_t h0, l0, h1, l1;
            split2(kv.x, kv.y, h0, l0);
            split2(kv.z, kv.w, h1, l1);
            uint2 hh; hh.x = h0; hh.y = h1;
            uint2 ll; ll.x = l0; ll.y = l1;
            *(uint2*)(Khi + ((size_t)r*QSTR + c4*4)*2) = hh;
            *(uint2*)(Klo + ((size_t)r*QSTR + c4*4)*2) = ll;
        }
        __syncthreads();   // (b) K planes visible

        // ---- E = Q K^T : 16x16 per warp, split-bf16, 36 MMAs ----
        float eacc[2][4];
        #pragma unroll
        for (int j = 0; j < 2; j++)
            #pragma unroll
            for (int r = 0; r < 4; r++) eacc[j][r] = 0.f;

        #pragma unroll
        for (int s = 0; s < 6; s++) {
            const int cA = hb + s*16 + tig*2;
            uint32_t ah[4], al[4], bh[2][2], bl[2][2];
            {
                const size_t ro = (size_t)gid*QSTR + cA;
                const char* ph = Qhi + ro*2;
                ah[0] = *(const uint32_t*)(ph);
                ah[1] = *(const uint32_t*)(ph + (size_t)8*QSTR*2);
                ah[2] = *(const uint32_t*)(ph + 16);
                ah[3] = *(const uint32_t*)(ph + (size_t)8*QSTR*2 + 16);
                const char* pl = Qlo + ro*2;
                al[0] = *(const uint32_t*)(pl);
                al[1] = *(const uint32_t*)(pl + (size_t)8*QSTR*2);
                al[2] = *(const uint32_t*)(pl + 16);
                al[3] = *(const uint32_t*)(pl + (size_t)8*QSTR*2 + 16);
            }
            #pragma unroll
            for (int j = 0; j < 2; j++) {
                const size_t ro = (size_t)(j*8 + gid)*QSTR + cA;
                const char* ph = Khi + ro*2;
                bh[j][0] = *(const uint32_t*)(ph);
                bh[j][1] = *(const uint32_t*)(ph + 16);
                const char* pl = Klo + ro*2;
                bl[j][0] = *(const uint32_t*)(pl);
                bl[j][1] = *(const uint32_t*)(pl + 16);
            }
            #pragma unroll
            for (int j = 0; j < 2; j++) {
                mma_bf16(eacc[j], ah, bh[j]);
                mma_bf16(eacc[j], ah, bl[j]);
                mma_bf16(eacc[j], al, bh[j]);
            }
        }

        // exp -> Es (fp32)
        #pragma unroll
        for (int j = 0; j < 2; j++) {
            const int r0 = warp*TQ + gid;
            const int c0 = j*8 + tig*2;
            Es[(r0    )*ESTR + c0    ] = __expf(eacc[j][0]);
            Es[(r0    )*ESTR + c0 + 1] = __expf(eacc[j][1]);
            Es[(r0 + 8)*ESTR + c0    ] = __expf(eacc[j][2]);
            Es[(r0 + 8)*ESTR + c0 + 1] = __expf(eacc[j][3]);
        }
        __syncthreads();   // (c) all E reads of K planes done; Es visible

        // ---- V tile -> fp32 into the SAME buffer (overwrites K planes) ----
        for (int j = tid; j < TK*(EMD/4); j += 256) {
            const int r  = j / (EMD/4);
            const int c4 = j % (EMD/4);
            *(float4*)(Vs + (size_t)r*VSTR + c4*4) =
                *(const float4*)(g_V + (size_t)(b*SEQ + k0 + r)*EMD + c4*4);
        }

        // Cross-head denominator + in-place normalize: one (q,k) per thread
        {
            const int q = tid >> 4;
            const int k = tid & 15;
            float s = 0.f;
            #pragma unroll
            for (int h = 0; h < HEADS; h++) s += Es[(h*TQ + q)*ESTR + k];
            const float inv = 1.0f / (s * SQRT_EMD);
            #pragma unroll
            for (int h = 0; h < HEADS; h++) Es[(h*TQ + q)*ESTR + k] *= inv;
        }
        __syncthreads();   // (d) V + normalized Es visible

        // ---- O += A @ V (FFMA2): rows qg+4i (i<4), d-cols kg*12..+11 ----
        #pragma unroll
        for (int k = 0; k < TK; k++) {
            ull a2[4];
            #pragma unroll
            for (int i = 0; i < 4; i++) {
                const float av = Es[(warp*TQ + qg + 4*i)*ESTR + k];
                a2[i] = pk2(av, av);
            }
            const float* vp = Vs + (size_t)k*VSTR + hb + kg*12;
            const ulonglong2 v0 = *(const ulonglong2*)(vp + 0);
            const ulonglong2 v1 = *(const ulonglong2*)(vp + 4);
            const ulonglong2 v2 = *(const ulonglong2*)(vp + 8);
            #pragma unroll
            for (int i = 0; i < 4; i++) {
                FFMA2(Oacc[i][0], a2[i], v0.x, Oacc[i][0]);
                FFMA2(Oacc[i][1], a2[i], v0.y, Oacc[i][1]);
                FFMA2(Oacc[i][2], a2[i], v1.x, Oacc[i][2]);
                FFMA2(Oacc[i][3], a2[i], v1.y, Oacc[i][3]);
                FFMA2(Oacc[i][4], a2[i], v2.x, Oacc[i][4]);
                FFMA2(Oacc[i][5], a2[i], v2.y, Oacc[i][5]);
            }
        }
    }

    // Write partial O in [M, 768] layout (col = h*96 + d)
    float* Obase = (kh == 0) ? g_O0 : (kh == 1) ? g_O1 : (kh == 2) ? g_O2 : g_O3;
    #pragma unroll
    for (int i = 0; i < 4; i++) {
        float* op = Obase + (size_t)(b*SEQ + q0 + qg + 4*i)*EMD + hb + kg*12;
        float f[12];
        upk2(Oacc[i][0], f[0], f[1]);  upk2(Oacc[i][1], f[2],  f[3]);
        upk2(Oacc[i][2], f[4], f[5]);  upk2(Oacc[i][3], f[6],  f[7]);
        upk2(Oacc[i][4], f[8], f[9]);  upk2(Oacc[i][5], f[10], f[11]);
        float4 o0, o1, o2;
        o0.x=f[0]; o0.y=f[1]; o0.z=f[2];  o0.w=f[3];
        o1.x=f[4]; o1.y=f[5]; o1.z=f[6];  o1.w=f[7];
        o2.x=f[8]; o2.y=f[9]; o2.z=f[10]; o2.w=f[11];
        *(float4*)(op + 0) = o0;
        *(float4*)(op + 4) = o1;
        *(float4*)(op + 8) = o2;
    }
}

// ---------------------------------------------------------------------------
extern "C" void kernel_launch(void* const* d_in, const int* in_sizes, int n_in,
                              void* d_out, int out_size)
{
    const float* x  = (const float*)d_in[0];
    const float* Wq = (const float*)d_in[1];
    const float* bq = (const float*)d_in[2];
    const float* Wk = (const float*)d_in[3];
    const float* bk = (const float*)d_in[4];
    const float* Wv = (const float*)d_in[5];
    const float* bv = (const float*)d_in[6];
    const float* Wo = (const float*)d_in[7];
    const float* bo = (const float*)d_in[8];
    float* out = (float*)d_out;

    float *Qp, *Kp, *Vp, *O0p;
    cudaGetSymbolAddress((void**)&Qp,  g_Q);
    cudaGetSymbolAddress((void**)&Kp,  g_K);
    cudaGetSymbolAddress((void**)&Vp,  g_V);
    cudaGetSymbolAddress((void**)&O0p, g_O0);

    const int smem_bytes = 108032;   // 2 CTAs/SM
    cudaFuncSetAttribute(attn_kernel, cudaFuncAttributeMaxDynamicSharedMemorySize, smem_bytes);

    // 1) Fused QKV projections (tf32 mma.sync; z selects Q/K/V)
    gemm_mma<<<dim3(MROWS/128, EMD/128, 3), 256>>>(
        x, Wq, bq, Qp, Wk, bk, Kp, Wv, bv, Vp);

    // 2) Fused head-axis-softmax attention, split-K4, TQ=16, 2 CTAs/SM
    attn_kernel<<<dim3(SEQ/TQ, BATCH, KSPLIT), 256, smem_bytes>>>();

    // 3) Sum split-K partials into g_O0
    presum_o<<<2048, 256>>>();

    // 4) Output projection (tf32 mma.sync) -> d_out
    gemm_mma<<<dim3(MROWS/128, EMD/128, 1), 256>>>(
        O0p, Wo, bo, out, Wo, bo, out, Wo, bo, out);
}

// round 14
// speedup vs baseline: 1.3108x; 1.3108x over previous
#include <cuda_runtime.h>
#include <math.h>
#include <stdint.h>

#define BATCH 4
#define SEQ   2048
#define EMD   768
#define HEADS 8
#define HDIM  96
#define MROWS (BATCH*SEQ)

#define TQ 32
#define TK 16
#define KSPLIT 4
#define KCHUNK (SEQ/KSPLIT)
#define QSTR 776           // bf16 elements per smem row (1552 B) -> conflict-free frags
#define ESTR 18            // Es stride (floats), even -> float2 stores
#define SQRT_EMD 27.712812921102035f

__device__ __forceinline__ uint32_t f2tf32(float x) {
    uint32_t r; asm("cvt.rna.tf32.f32 %0, %1;" : "=r"(r) : "f"(x)); return r;
}
// C(16x8,f32) += A(16x8,tf32,row) * B(8x8,tf32,col)
__device__ __forceinline__ void mma_tf32(float* d, const uint32_t* a, const uint32_t* b) {
    asm volatile(
        "mma.sync.aligned.m16n8k8.row.col.f32.tf32.tf32.f32 "
        "{%0,%1,%2,%3}, {%4,%5,%6,%7}, {%8,%9}, {%0,%1,%2,%3};"
        : "+f"(d[0]), "+f"(d[1]), "+f"(d[2]), "+f"(d[3])
        : "r"(a[0]), "r"(a[1]), "r"(a[2]), "r"(a[3]), "r"(b[0]), "r"(b[1]));
}
// C(16x8,f32) += A(16x16,bf16,row) * B(16x8,bf16,col)
__device__ __forceinline__ void mma_bf16(float* d, const uint32_t* a, const uint32_t* b) {
    asm volatile(
        "mma.sync.aligned.m16n8k16.row.col.f32.bf16.bf16.f32 "
        "{%0,%1,%2,%3}, {%4,%5,%6,%7}, {%8,%9}, {%0,%1,%2,%3};"
        : "+f"(d[0]), "+f"(d[1]), "+f"(d[2]), "+f"(d[3])
        : "r"(a[0]), "r"(a[1]), "r"(a[2]), "r"(a[3]), "r"(b[0]), "r"(b[1]));
}
__device__ __forceinline__ uint32_t bfx2(float lo, float hi) {
    uint32_t r; asm("cvt.rn.bf16x2.f32 %0, %1, %2;" : "=r"(r) : "f"(hi), "f"(lo)); return r;
}
// split (x,y) into hi-pair (bf16 rn) and lo-pair (residual as bf16); lo half = x
__device__ __forceinline__ void split2(float x, float y, uint32_t& hp, uint32_t& lp) {
    const uint32_t bx = __float_as_uint(x), by = __float_as_uint(y);
    const uint32_t rx = (bx + 0x7FFFu + ((bx >> 16) & 1u)) & 0xFFFF0000u;
    const uint32_t ry = (by + 0x7FFFu + ((by >> 16) & 1u)) & 0xFFFF0000u;
    hp = ry | (rx >> 16);
    lp = bfx2(x - __uint_as_float(rx), y - __uint_as_float(ry));
}
__device__ __forceinline__ uint32_t smem_u32(const void* p) {
    uint32_t a;
    asm("{ .reg .u64 t; cvta.to.shared.u64 t, %1; cvt.u32.u64 %0, t; }" : "=r"(a) : "l"(p));
    return a;
}
// 2x 8x8 b16 transposed tiles (B-fragment for m16n8k16)
__device__ __forceinline__ void ldmx2t(uint32_t& b0, uint32_t& b1, uint32_t addr) {
    asm volatile("ldmatrix.sync.aligned.m8n8.x2.trans.shared.b16 {%0,%1}, [%2];"
                 : "=r"(b0), "=r"(b1) : "r"(addr));
}

// Scratch (allocation-free rule: __device__ globals)
__device__ uint16_t g_Qhi[MROWS*EMD], g_Qlo[MROWS*EMD];
__device__ uint16_t g_Khi[MROWS*EMD], g_Klo[MROWS*EMD];
__device__ uint16_t g_Vhi[MROWS*EMD], g_Vlo[MROWS*EMD];
__device__ float g_O0[MROWS*EMD];
__device__ float g_O1[MROWS*EMD];
__device__ float g_O2[MROWS*EMD];
__device__ float g_O3[MROWS*EMD];

// ---------------------------------------------------------------------------
// mma.sync tf32 NT GEMM: C = A*W^T + bias. 128x128 tile, BK=32, 8 warps
// (2M x 4N), warp tile 64x32, fp32 accumulate, 2 CTAs/SM.
// Output: either fp32 C (H==0) or split-bf16 hi/lo planes (H,L != 0).
// blockIdx.z selects the (W,bias,out) triple for the fused QKV launch.
// ---------------------------------------------------------------------------
__global__ __launch_bounds__(256, 2)
void gemm_mma(const float* __restrict__ A,
              const float* __restrict__ W0, const float* __restrict__ bv0, float* __restrict__ C0,
              uint16_t* __restrict__ H0, uint16_t* __restrict__ L0,
              const float* __restrict__ W1, const float* __restrict__ bv1, float* __restrict__ C1,
              uint16_t* __restrict__ H1, uint16_t* __restrict__ L1,
              const float* __restrict__ W2, const float* __restrict__ bv2, float* __restrict__ C2,
              uint16_t* __restrict__ H2, uint16_t* __restrict__ L2)
{
    const float* W    = W0;
    const float* bias = bv0;
    float*       C    = C0;
    uint16_t*    H    = H0;
    uint16_t*    L    = L0;
    if (blockIdx.z == 1) { W = W1; bias = bv1; C = C1; H = H1; L = L1; }
    if (blockIdx.z == 2) { W = W2; bias = bv2; C = C2; H = H2; L = L2; }

    __shared__ __align__(16) uint32_t As[128][36];
    __shared__ __align__(16) uint32_t Bs[128][36];

    const int tid  = threadIdx.x;
    const int w    = tid >> 5;
    const int lane = tid & 31;
    const int wm   = w & 1;
    const int wn   = w >> 1;
    const int gid  = lane >> 2;
    const int tig  = lane & 3;
    const int m0   = blockIdx.x * 128;
    const int n0   = blockIdx.y * 128;

    const int lr = tid >> 1;
    const int lc = (tid & 1) * 16;

    const float* Ap = A + (size_t)(m0 + lr) * EMD + lc;
    const float* Wp = W + (size_t)(n0 + lr) * EMD + lc;

    float acc[4][4][4];
    #pragma unroll
    for (int i = 0; i < 4; i++)
        #pragma unroll
        for (int j = 0; j < 4; j++)
            #pragma unroll
            for (int r = 0; r < 4; r++) acc[i][j][r] = 0.f;

    for (int k0 = 0; k0 < EMD; k0 += 32) {
        #pragma unroll
        for (int ci = 0; ci < 4; ci++) {
            const float4 v  = *(const float4*)(Ap + k0 + ci*4);
            uint4 t;
            t.x = f2tf32(v.x); t.y = f2tf32(v.y); t.z = f2tf32(v.z); t.w = f2tf32(v.w);
            *(uint4*)&As[lr][lc + ci*4] = t;
            const float4 wv = *(const float4*)(Wp + k0 + ci*4);
            uint4 u;
            u.x = f2tf32(wv.x); u.y = f2tf32(wv.y); u.z = f2tf32(wv.z); u.w = f2tf32(wv.w);
            *(uint4*)&Bs[lr][lc + ci*4] = u;
        }
        __syncthreads();

        #pragma unroll
        for (int ks = 0; ks < 4; ks++) {
            uint32_t a[4][4], b[4][2];
            #pragma unroll
            for (int i = 0; i < 4; i++) {
                const uint32_t* ap = &As[wm*64 + i*16 + gid][ks*8 + tig];
                a[i][0] = ap[0];
                a[i][1] = ap[8*36];
                a[i][2] = ap[4];
                a[i][3] = ap[8*36 + 4];
            }
            #pragma unroll
            for (int j = 0; j < 4; j++) {
                const uint32_t* bp = &Bs[wn*32 + j*8 + gid][ks*8 + tig];
                b[j][0] = bp[0];
                b[j][1] = bp[4];
            }
            #pragma unroll
            for (int i = 0; i < 4; i++)
                #pragma unroll
                for (int j = 0; j < 4; j++)
                    mma_tf32(acc[i][j], a[i], b[j]);
        }
        __syncthreads();
    }

    #pragma unroll
    for (int i = 0; i < 4; i++) {
        const int m = m0 + wm*64 + i*16 + gid;
        #pragma unroll
        for (int j = 0; j < 4; j++) {
            const int n = n0 + wn*32 + j*8 + tig*2;
            const float2 bv = *(const float2*)&bias[n];
            float2 o0, o1;
            o0.x = acc[i][j][0] + bv.x; o0.y = acc[i][j][1] + bv.y;
            o1.x = acc[i][j][2] + bv.x; o1.y = acc[i][j][3] + bv.y;
            if (H) {   // split-bf16 hi/lo plane output (for attention inputs)
                uint32_t hp, lp;
                split2(o0.x, o0.y, hp, lp);
                *(uint32_t*)(H + (size_t)m*EMD + n) = hp;
                *(uint32_t*)(L + (size_t)m*EMD + n) = lp;
                split2(o1.x, o1.y, hp, lp);
                *(uint32_t*)(H + (size_t)(m+8)*EMD + n) = hp;
                *(uint32_t*)(L + (size_t)(m+8)*EMD + n) = lp;
            } else {
                *(float2*)(C + (size_t)m*EMD + n)     = o0;
                *(float2*)(C + (size_t)(m+8)*EMD + n) = o1;
            }
        }
    }
}

// ---------------------------------------------------------------------------
// Sum the 4 split-K partial O buffers into g_O0 (float4 grid-stride).
// ---------------------------------------------------------------------------
__global__ __launch_bounds__(256)
void presum_o()
{
    const size_t N = (size_t)MROWS * EMD / 4;
    float4*       o0 = (float4*)g_O0;
    const float4* o1 = (const float4*)g_O1;
    const float4* o2 = (const float4*)g_O2;
    const float4* o3 = (const float4*)g_O3;
    for (size_t i = (size_t)blockIdx.x * blockDim.x + threadIdx.x; i < N;
         i += (size_t)gridDim.x * blockDim.x) {
        float4 a = o0[i];
        const float4 b = o1[i], c = o2[i], d = o3[i];
        a.x = (a.x + b.x) + (c.x + d.x);
        a.y = (a.y + b.y) + (c.y + d.y);
        a.z = (a.z + b.z) + (c.z + d.z);
        a.w = (a.w + b.w) + (c.w + d.w);
        o0[i] = a;
    }
}

// ---------------------------------------------------------------------------
// Fused attention, softmax over HEADS axis. Split-K4, TQ=32.
// E  = Q K^T  via split-bf16 m16n8k16 (hi/lo planes, precomputed in GEMM).
// AV = A V    via split-bf16 m16n8k16: A-fragments built IN REGISTERS from the
//              E C-fragments (identical layout), scaled by cross-head 1/denom;
//              V B-fragments via ldmatrix.x2.trans from [k][d] bf16 planes.
// CTA: (b, 32-row q-tile, k-quarter). 8 warps = 1 per head.
// Smem: Qhi/Qlo [32][776], Khi/Klo [16][776], Vhi/Vlo [16][776] (bf16),
//       Es f32[8*32][18], Dinv f32[32][18]  -> 219392 B.
// ---------------------------------------------------------------------------
__global__ __launch_bounds__(256)
void attn_kernel()
{
    extern __shared__ char smx[];
    uint16_t* Qhi = (uint16_t*)(smx);            // 49664
    uint16_t* Qlo = (uint16_t*)(smx + 49664);    // 49664
    uint16_t* Khi = (uint16_t*)(smx + 99328);    // 24832
    uint16_t* Klo = (uint16_t*)(smx + 124160);   // 24832
    uint16_t* Vhi = (uint16_t*)(smx + 148992);   // 24832
    uint16_t* Vlo = (uint16_t*)(smx + 173824);   // 24832
    float*    Es  = (float*)   (smx + 198656);   // 18432
    float*    Dinv= (float*)   (smx + 217088);   // 2304

    const int b    = blockIdx.y;
    const int q0   = blockIdx.x * TQ;
    const int kh   = blockIdx.z;
    const int tid  = threadIdx.x;
    const int warp = tid >> 5;              // head
    const int lane = tid & 31;
    const int gid  = lane >> 2;             // 0..7
    const int tig  = lane & 3;              // 0..3
    const int hb   = warp * HDIM;           // head col base

    // ---- Q planes -> smem (once per CTA): straight bf16 copies ----
    for (int j = tid; j < TQ*(EMD/8); j += 256) {
        const int r  = j / (EMD/8);
        const int c8 = (j % (EMD/8)) * 8;
        const size_t g = (size_t)(b*SEQ + q0 + r)*EMD + c8;
        *(uint4*)(Qhi + (size_t)r*QSTR + c8) = *(const uint4*)(g_Qhi + g);
        *(uint4*)(Qlo + (size_t)r*QSTR + c8) = *(const uint4*)(g_Qlo + g);
    }

    float Oacc[2][12][4];
    #pragma unroll
    for (int i = 0; i < 2; i++)
        #pragma unroll
        for (int jj = 0; jj < 12; jj++)
            #pragma unroll
            for (int r = 0; r < 4; r++) Oacc[i][jj][r] = 0.f;

    // ldmatrix lane address bases (rows 0..15 of V planes, head col base)
    const uint32_t vhiA = smem_u32(Vhi) + (uint32_t)((lane & 15) * QSTR + hb) * 2u;
    const uint32_t vloA = smem_u32(Vlo) + (uint32_t)((lane & 15) * QSTR + hb) * 2u;

    const int kbeg = kh * KCHUNK;
    for (int k0 = kbeg; k0 < kbeg + KCHUNK; k0 += TK) {
        __syncthreads();   // prev AV reads of V/Es done; Q planes visible (iter 0)

        // ---- K,V planes -> smem: straight bf16 copies ----
        for (int j = tid; j < TK*(EMD/8); j += 256) {
            const int r  = j / (EMD/8);
            const int c8 = (j % (EMD/8)) * 8;
            const size_t g = (size_t)(b*SEQ + k0 + r)*EMD + c8;
            const size_t so = (size_t)r*QSTR + c8;
            *(uint4*)(Khi + so) = *(const uint4*)(g_Khi + g);
            *(uint4*)(Klo + so) = *(const uint4*)(g_Klo + g);
            *(uint4*)(Vhi + so) = *(const uint4*)(g_Vhi + g);
            *(uint4*)(Vlo + so) = *(const uint4*)(g_Vlo + g);
        }
        __syncthreads();

        // ---- E = Q K^T : 32x16 per warp, split-bf16, 72 MMAs ----
        float eacc[2][2][4];
        #pragma unroll
        for (int i = 0; i < 2; i++)
            #pragma unroll
            for (int j = 0; j < 2; j++)
                #pragma unroll
                for (int r = 0; r < 4; r++) eacc[i][j][r] = 0.f;

        #pragma unroll
        for (int s = 0; s < 6; s++) {
            const int cA = hb + s*16 + tig*2;
            uint32_t ah[2][4], al[2][4], bh[2][2], bl[2][2];
            #pragma unroll
            for (int i = 0; i < 2; i++) {
                const size_t ro = (size_t)(i*16 + gid)*QSTR + cA;
                const uint16_t* ph = Qhi + ro;
                ah[i][0] = *(const uint32_t*)(ph);
                ah[i][1] = *(const uint32_t*)(ph + (size_t)8*QSTR);
                ah[i][2] = *(const uint32_t*)(ph + 8);
                ah[i][3] = *(const uint32_t*)(ph + (size_t)8*QSTR + 8);
                const uint16_t* pl = Qlo + ro;
                al[i][0] = *(const uint32_t*)(pl);
                al[i][1] = *(const uint32_t*)(pl + (size_t)8*QSTR);
                al[i][2] = *(const uint32_t*)(pl + 8);
                al[i][3] = *(const uint32_t*)(pl + (size_t)8*QSTR + 8);
            }
            #pragma unroll
            for (int j = 0; j < 2; j++) {
                const size_t ro = (size_t)(j*8 + gid)*QSTR + cA;
                const uint16_t* ph = Khi + ro;
                bh[j][0] = *(const uint32_t*)(ph);
                bh[j][1] = *(const uint32_t*)(ph + 8);
                const uint16_t* pl = Klo + ro;
                bl[j][0] = *(const uint32_t*)(pl);
                bl[j][1] = *(const uint32_t*)(pl + 8);
            }
            #pragma unroll
            for (int i = 0; i < 2; i++)
                #pragma unroll
                for (int j = 0; j < 2; j++) {
                    mma_bf16(eacc[i][j], ah[i], bh[j]);
                    mma_bf16(eacc[i][j], ah[i], bl[j]);
                    mma_bf16(eacc[i][j], al[i], bh[j]);
                }
        }

        // ---- exp in registers; copies to Es for the denominator ----
        float ex[2][2][4];
        #pragma unroll
        for (int i = 0; i < 2; i++) {
            const int r0 = warp*TQ + i*16 + gid;
            #pragma unroll
            for (int j = 0; j < 2; j++) {
                const int c0 = j*8 + tig*2;
                ex[i][j][0] = __expf(eacc[i][j][0]);
                ex[i][j][1] = __expf(eacc[i][j][1]);
                ex[i][j][2] = __expf(eacc[i][j][2]);
                ex[i][j][3] = __expf(eacc[i][j][3]);
                float2 e0; e0.x = ex[i][j][0]; e0.y = ex[i][j][1];
                float2 e1; e1.x = ex[i][j][2]; e1.y = ex[i][j][3];
                *(float2*)&Es[(r0    )*ESTR + c0] = e0;
                *(float2*)&Es[(r0 + 8)*ESTR + c0] = e1;
            }
        }
        __syncthreads();

        // ---- cross-head denominator -> Dinv (2 (q,k) pairs per thread) ----
        #pragma unroll
        for (int pp = 0; pp < 2; pp++) {
            const int p = tid*2 + pp;
            const int q = p >> 4;
            const int k = p & 15;
            float s = 0.f;
            #pragma unroll
            for (int h = 0; h < HEADS; h++) s += Es[(h*TQ + q)*ESTR + k];
            Dinv[q*ESTR + k] = 1.0f / (s * SQRT_EMD);
        }
        __syncthreads();

        // ---- A-fragments in registers: a = exp * inv, split-bf16 ----
        uint32_t Ah[2][4], Al[2][4];
        #pragma unroll
        for (int i = 0; i < 2; i++) {
            const int r0 = (i*16 + gid)*ESTR;
            const int r1 = (i*16 + gid + 8)*ESTR;
            const float2 i00 = *(const float2*)&Dinv[r0 + tig*2];
            const float2 i10 = *(const float2*)&Dinv[r1 + tig*2];
            const float2 i01 = *(const float2*)&Dinv[r0 + tig*2 + 8];
            const float2 i11 = *(const float2*)&Dinv[r1 + tig*2 + 8];
            split2(ex[i][0][0]*i00.x, ex[i][0][1]*i00.y, Ah[i][0], Al[i][0]);
            split2(ex[i][0][2]*i10.x, ex[i][0][3]*i10.y, Ah[i][1], Al[i][1]);
            split2(ex[i][1][0]*i01.x, ex[i][1][1]*i01.y, Ah[i][2], Al[i][2]);
            split2(ex[i][1][2]*i11.x, ex[i][1][3]*i11.y, Ah[i][3], Al[i][3]);
        }

        // ---- O += A @ V : V B-frags via ldmatrix.trans, 72 MMAs ----
        #pragma unroll
        for (int jj = 0; jj < 12; jj++) {
            uint32_t bh[2], bl[2];
            ldmx2t(bh[0], bh[1], vhiA + jj*16);
            ldmx2t(bl[0], bl[1], vloA + jj*16);
            #pragma unroll
            for (int i = 0; i < 2; i++) {
                mma_bf16(Oacc[i][jj], Ah[i], bh);
                mma_bf16(Oacc[i][jj], Ah[i], bl);
                mma_bf16(Oacc[i][jj], Al[i], bh);
            }
        }
    }

    // ---- write partial O in [M, 768] layout (col = h*96 + d) ----
    float* Obase = (kh == 0) ? g_O0 : (kh == 1) ? g_O1 : (kh == 2) ? g_O2 : g_O3;
    #pragma unroll
    for (int i = 0; i < 2; i++) {
        const size_t r0 = (size_t)(b*SEQ + q0 + i*16 + gid);
        #pragma unroll
        for (int jj = 0; jj < 12; jj++) {
            const int n = hb + jj*8 + tig*2;
            float2 o0; o0.x = Oacc[i][jj][0]; o0.y = Oacc[i][jj][1];
            float2 o1; o1.x = Oacc[i][jj][2]; o1.y = Oacc[i][jj][3];
            *(float2*)(Obase + r0*EMD + n)       = o0;
            *(float2*)(Obase + (r0+8)*EMD + n)   = o1;
        }
    }
}

// ---------------------------------------------------------------------------
extern "C" void kernel_launch(void* const* d_in, const int* in_sizes, int n_in,
                              void* d_out, int out_size)
{
    const float* x  = (const float*)d_in[0];
    const float* Wq = (const float*)d_in[1];
    const float* bq = (const float*)d_in[2];
    const float* Wk = (const float*)d_in[3];
    const float* bk = (const float*)d_in[4];
    const float* Wv = (const float*)d_in[5];
    const float* bv = (const float*)d_in[6];
    const float* Wo = (const float*)d_in[7];
    const float* bo = (const float*)d_in[8];
    float* out = (float*)d_out;

    float *O0p;
    uint16_t *Qh, *Ql, *Kh, *Kl, *Vh, *Vl;
    cudaGetSymbolAddress((void**)&O0p, g_O0);
    cudaGetSymbolAddress((void**)&Qh,  g_Qhi);
    cudaGetSymbolAddress((void**)&Ql,  g_Qlo);
    cudaGetSymbolAddress((void**)&Kh,  g_Khi);
    cudaGetSymbolAddress((void**)&Kl,  g_Klo);
    cudaGetSymbolAddress((void**)&Vh,  g_Vhi);
    cudaGetSymbolAddress((void**)&Vl,  g_Vlo);

    const int smem_bytes = 219392;
    cudaFuncSetAttribute(attn_kernel, cudaFuncAttributeMaxDynamicSharedMemorySize, smem_bytes);

    // 1) Fused QKV projections -> split-bf16 hi/lo planes (z selects Q/K/V)
    gemm_mma<<<dim3(MROWS/128, EMD/128, 3), 256>>>(
        x,
        Wq, bq, (float*)0, Qh, Ql,
        Wk, bk, (float*)0, Kh, Kl,
        Wv, bv, (float*)0, Vh, Vl);

    // 2) Fused head-axis-softmax attention, split-K4, all-tensor-pipe core
    attn_kernel<<<dim3(SEQ/TQ, BATCH, KSPLIT), 256, smem_bytes>>>();

    // 3) Sum split-K partials into g_O0
    presum_o<<<2048, 256>>>();

    // 4) Output projection (tf32 mma.sync, fp32 out) -> d_out
    gemm_mma<<<dim3(MROWS/128, EMD/128, 1), 256>>>(
        O0p,
        Wo, bo, out, (uint16_t*)0, (uint16_t*)0,
        Wo, bo, out, (uint16_t*)0, (uint16_t*)0,
        Wo, bo, out, (uint16_t*)0, (uint16_t*)0);
}